// round 2
// baseline (speedup 1.0000x reference)
#include <cuda_runtime.h>
#include <cuda_bf16.h>
#include <cstdint>

// Problem constants
#define BB   8
#define LL   50
#define BL   400     // B*L
#define MM   32
#define NHOP 2
#define DD   64
#define HH   2
#define HDD  32
#define RR   20
#define NBLK 2

// ---------------- scratch (device globals; no allocation allowed) ------------
__device__ float g_item [BL*DD];
__device__ float g_item0[BL*DD];
__device__ float g_osum [BL*DD];
__device__ float g_V    [BL*RR*DD];   // V[bl][r][j] = item(bl)^T R_r
__device__ float g_x    [BL*DD];
__device__ float g_Q    [BL*DD];
__device__ float g_q    [BL*DD];
__device__ float g_k    [BL*DD];
__device__ float g_v    [BL*DD];
__device__ float g_ctx  [BL*DD];

__device__ __forceinline__ float lrelu(float x) { return x > 0.f ? x : 0.01f * x; }

// ---------------- K0: item0 = E[seq], item=item0, osum=0 ---------------------
__global__ void k_init(const float* __restrict__ E, const int* __restrict__ seq)
{
    int bl = blockIdx.x, t = threadIdx.x;      // 64 threads
    float v = E[(long)seq[bl] * DD + t];
    g_item [bl*DD + t] = v;
    g_item0[bl*DD + t] = v;
    g_osum [bl*DD + t] = 0.f;
}

// ---------------- K1: V[bl,r,:] = item(bl)^T R_r  ----------------------------
// grid (RR, 8) : block = (relation r, chunk of 50 items). 256 threads.
__global__ __launch_bounds__(256) void k_vcomp(const float* __restrict__ rel)
{
    __shared__ float RT[DD*68];     // transposed R, padded stride 68 (16B aligned)
    __shared__ float IT[50*DD];     // 50 item rows
    int r = blockIdx.x, chunk = blockIdx.y;
    int t = threadIdx.x;

    const float* Rr = rel + (long)r * (DD*DD);
    for (int idx = t; idx < DD*DD; idx += 256) {
        int i = idx >> 6, j = idx & 63;
        RT[j*68 + i] = Rr[idx];
    }
    int base = chunk * 50 * DD;
    for (int idx = t; idx < 50*DD; idx += 256)
        IT[idx] = g_item[base + idx];
    __syncthreads();

    int j = t & 63, g = t >> 6;     // g in 0..3
    const float4* rtj = (const float4*)(RT + j*68);
    for (int p = g; p < 25; p += 4) {
        int l0 = 2*p, l1 = 2*p + 1;
        const float4* i0 = (const float4*)(IT + l0*DD);
        const float4* i1 = (const float4*)(IT + l1*DD);
        float a0 = 0.f, a1 = 0.f;
        #pragma unroll
        for (int kk = 0; kk < 16; kk++) {
            float4 w  = rtj[kk];
            float4 x0 = i0[kk];
            float4 x1 = i1[kk];
            a0 += w.x*x0.x + w.y*x0.y + w.z*x0.z + w.w*x0.w;
            a1 += w.x*x1.x + w.y*x1.y + w.z*x1.z + w.w*x1.w;
        }
        int bl0 = chunk*50 + l0;
        g_V[((long)bl0      * RR + r) * DD + j] = a0;
        g_V[((long)(bl0+1)  * RR + r) * DD + j] = a1;
    }
}

// ---------------- K2: per-(b,l) hop update -----------------------------------
// scores -> softmax -> o -> osum += o -> item = lrelu((o+item)@Wt^T)
__global__ __launch_bounds__(128) void k_hop(
    const float* __restrict__ E, const float* __restrict__ Wt,
    const int* __restrict__ mh, const int* __restrict__ mr, const int* __restrict__ mt,
    int hop, int last)
{
    __shared__ float sc[MM], pr[MM], u[DD], part[128], item_s[DD];
    int bl = blockIdx.x, t = threadIdx.x;
    if (t < DD) item_s[t] = g_item[bl*DD + t];

    // scores: 4 threads per m, 16 elems each
    int m = t >> 2, q4 = t & 3;
    int midx = (bl*NHOP + hop) * MM + m;
    int hid = mh[midx], rid = mr[midx];
    const float4* Vv = (const float4*)(g_V + ((long)bl*RR + rid) * DD) + q4*4;
    const float4* Hh = (const float4*)(E + (long)hid * DD) + q4*4;
    float acc = 0.f;
    #pragma unroll
    for (int i = 0; i < 4; i++) {
        float4 a = Vv[i], b = Hh[i];
        acc += a.x*b.x + a.y*b.y + a.z*b.z + a.w*b.w;
    }
    acc += __shfl_down_sync(0xffffffffu, acc, 2, 4);
    acc += __shfl_down_sync(0xffffffffu, acc, 1, 4);
    if (q4 == 0) sc[m] = acc;
    __syncthreads();

    // softmax over 32 m (warp 0)
    if (t < 32) {
        float v = sc[t];
        float mx = v;
        #pragma unroll
        for (int o = 16; o; o >>= 1) mx = fmaxf(mx, __shfl_xor_sync(0xffffffffu, mx, o));
        float e = __expf(v - mx);
        float s = e;
        #pragma unroll
        for (int o = 16; o; o >>= 1) s += __shfl_xor_sync(0xffffffffu, s, o);
        pr[t] = e / s;
    }
    __syncthreads();

    // o[d] = sum_m pr[m]*E[t_m][d]  (split m over two halves)
    int d = t & 63, half = t >> 6;
    float od = 0.f;
    #pragma unroll 4
    for (int m2 = half*16; m2 < half*16 + 16; m2++) {
        int te = mt[(bl*NHOP + hop) * MM + m2];
        od += pr[m2] * E[(long)te * DD + d];
    }
    part[t] = od;
    __syncthreads();
    if (t < DD) {
        float o = part[t] + part[t + 64];
        g_osum[bl*DD + t] += o;
        u[t] = o + item_s[t];
    }
    __syncthreads();

    if (!last) {
        // item = lrelu(u @ Wt^T)
        const float4* wr = (const float4*)(Wt + d*DD) + half*8;
        const float4* uu = (const float4*)u + half*8;
        float a = 0.f;
        #pragma unroll
        for (int kk = 0; kk < 8; kk++) {
            float4 w = wr[kk], x = uu[kk];
            a += w.x*x.x + w.y*x.y + w.z*x.z + w.w*x.w;
        }
        part[t] = a;
        __syncthreads();
        if (t < DD) {
            float s = part[t] + part[t + 64];
            g_item[bl*DD + t] = lrelu(s);
        }
    }
}

// ---------------- K3: sequential interest scan (per batch b) -----------------
// 8 blocks x 128 threads. thread: i = t&63 (output elem), path = t>>6 (W1/W2).
__global__ __launch_bounds__(128) void k_scan(
    const float* __restrict__ W1, const float* __restrict__ W2,
    const float* __restrict__ uemb, const int* __restrict__ user,
    const float* __restrict__ pemb)
{
    __shared__ float S[LL*DD];
    __shared__ float AB[128];
    __shared__ float T[128];
    int b = blockIdx.x, t = threadIdx.x;
    int i = t & 63, path = t >> 6;

    // weights: row i of W_path, held in registers
    const float* W = path ? W2 : W1;
    const float4* wr = (const float4*)(W + i*DD);
    float4 wv[16];
    #pragma unroll
    for (int kk = 0; kk < 16; kk++) wv[kk] = wr[kk];

    // user_short = item0 + osum staged to smem
    for (int idx = t; idx < LL*DD; idx += 128)
        S[idx] = g_item0[b*LL*DD + idx] + g_osum[b*LL*DD + idx];

    float c = uemb[(long)user[b] * DD + i];
    __syncthreads();

    for (int st = 0; st < LL; st++) {
        float sv = S[st*DD + i];
        AB[path*64 + i] = path ? (sv * c) : (sv + c);
        __syncthreads();
        const float4* in = (const float4*)(AB + path*64);
        float a0 = 0.f, a1 = 0.f, a2 = 0.f, a3 = 0.f;
        #pragma unroll
        for (int kk = 0; kk < 16; kk += 4) {
            float4 x0 = in[kk],   x1 = in[kk+1], x2 = in[kk+2], x3 = in[kk+3];
            a0 += wv[kk  ].x*x0.x + wv[kk  ].y*x0.y + wv[kk  ].z*x0.z + wv[kk  ].w*x0.w;
            a1 += wv[kk+1].x*x1.x + wv[kk+1].y*x1.y + wv[kk+1].z*x1.z + wv[kk+1].w*x1.w;
            a2 += wv[kk+2].x*x2.x + wv[kk+2].y*x2.y + wv[kk+2].z*x2.z + wv[kk+2].w*x2.w;
            a3 += wv[kk+3].x*x3.x + wv[kk+3].y*x3.y + wv[kk+3].z*x3.z + wv[kk+3].w*x3.w;
        }
        float r = lrelu((a0 + a1) + (a2 + a3));
        T[path*64 + i] = r;
        __syncthreads();
        float out = T[i] + T[64 + i];
        c = out;
        if (path == 0)
            g_x[(b*LL + st)*DD + i] = out * 8.0f + pemb[st*DD + i];
    }
}

// ---------------- K4: per-row LN -> Q, then q/k/v projections ----------------
__global__ __launch_bounds__(128) void k_lnqkv(
    const float* __restrict__ lns, const float* __restrict__ lnb,
    const float* __restrict__ ipw, const float* __restrict__ ipb, int bb)
{
    __shared__ float xs[DD], Qs[DD];
    __shared__ float mv[2];
    int bl = blockIdx.x, t = threadIdx.x;
    if (t < DD) xs[t] = g_x[bl*DD + t];
    __syncthreads();
    if (t < 32) {
        float s = xs[t] + xs[t + 32];
        #pragma unroll
        for (int o = 16; o; o >>= 1) s += __shfl_xor_sync(0xffffffffu, s, o);
        float mean = s * (1.f/64.f);
        float d0 = xs[t] - mean, d1 = xs[t+32] - mean;
        float vs = d0*d0 + d1*d1;
        #pragma unroll
        for (int o = 16; o; o >>= 1) vs += __shfl_xor_sync(0xffffffffu, vs, o);
        if (t == 0) { mv[0] = mean; mv[1] = rsqrtf(vs * (1.f/64.f) + 1e-8f); }
    }
    __syncthreads();
    if (t < DD) {
        float q = (xs[t] - mv[0]) * mv[1] * lns[bb*DD + t] + lnb[bb*DD + t];
        Qs[t] = q;
        g_Q[bl*DD + t] = q;
    }
    __syncthreads();

    for (int o = t; o < 3*DD; o += 128) {
        const float* src = (o < DD) ? Qs : xs;          // q from Q, k/v from x
        const float4* w4 = (const float4*)(ipw + ((long)bb*3*DD + o) * DD);
        const float4* s4 = (const float4*)src;
        float acc = 0.f;
        #pragma unroll
        for (int kk = 0; kk < 16; kk++) {
            float4 w = w4[kk], x = s4[kk];
            acc += w.x*x.x + w.y*x.y + w.z*x.z + w.w*x.w;
        }
        acc += ipb[bb*3*DD + o];
        if      (o < DD)   g_q[bl*DD + o      ] = acc;
        else if (o < 2*DD) g_k[bl*DD + o - 64 ] = acc;
        else               g_v[bl*DD + o - 128] = acc;
    }
}

// ---------------- K5: causal attention, block = (b,h) ------------------------
__global__ __launch_bounds__(256) void k_attn()
{
    __shared__ float qh[LL*36], kh[LL*36], vh[LL*36];
    __shared__ float ps[8][52];
    int blk = blockIdx.x, b = blk >> 1, h = blk & 1, t = threadIdx.x;

    for (int idx = t; idx < LL*HDD; idx += 256) {
        int l = idx >> 5, d = idx & 31;
        int src = (b*LL + l)*DD + h*HDD + d;
        qh[l*36 + d] = g_q[src];
        kh[l*36 + d] = g_k[src];
        vh[l*36 + d] = g_v[src];
    }
    __syncthreads();

    int w = t >> 5, lane = t & 31;
    const float scl = 0.17677669529663687f;   // 1/sqrt(32)
    for (int qi = w; qi < LL; qi += 8) {
        float4 qreg[8];
        const float4* qa = (const float4*)(qh + qi*36);
        #pragma unroll
        for (int kk = 0; kk < 8; kk++) qreg[kk] = qa[kk];

        int k0 = lane, k1 = lane + 32;
        float s0 = -3.0e38f, s1 = -3.0e38f;
        if (k0 <= qi) {
            const float4* ka = (const float4*)(kh + k0*36);
            float a = 0.f;
            #pragma unroll
            for (int kk = 0; kk < 8; kk++) {
                float4 kv = ka[kk];
                a += qreg[kk].x*kv.x + qreg[kk].y*kv.y + qreg[kk].z*kv.z + qreg[kk].w*kv.w;
            }
            s0 = a * scl;
        }
        if (k1 <= qi) {
            const float4* ka = (const float4*)(kh + k1*36);
            float a = 0.f;
            #pragma unroll
            for (int kk = 0; kk < 8; kk++) {
                float4 kv = ka[kk];
                a += qreg[kk].x*kv.x + qreg[kk].y*kv.y + qreg[kk].z*kv.z + qreg[kk].w*kv.w;
            }
            s1 = a * scl;
        }
        float mx = fmaxf(s0, s1);
        #pragma unroll
        for (int o = 16; o; o >>= 1) mx = fmaxf(mx, __shfl_xor_sync(0xffffffffu, mx, o));
        float e0 = (k0 <= qi) ? __expf(s0 - mx) : 0.f;
        float e1 = (k1 <= qi) ? __expf(s1 - mx) : 0.f;
        float sm = e0 + e1;
        #pragma unroll
        for (int o = 16; o; o >>= 1) sm += __shfl_xor_sync(0xffffffffu, sm, o);
        float inv = 1.f / sm;
        ps[w][k0] = e0 * inv;
        if (k1 < LL) ps[w][k1] = e1 * inv;
        __syncwarp();
        float acc = 0.f;
        for (int kj = 0; kj <= qi; kj++)
            acc += ps[w][kj] * vh[kj*36 + lane];
        g_ctx[(b*LL + qi)*DD + h*HDD + lane] = acc;
        __syncwarp();
    }
}

// ---------------- K6: out-proj + residual + LN + FFN + residual --------------
__global__ __launch_bounds__(128) void k_mlp(
    const float* __restrict__ opw, const float* __restrict__ opb,
    const float* __restrict__ fs,  const float* __restrict__ fb,
    const float* __restrict__ c1w, const float* __restrict__ c1b,
    const float* __restrict__ c2w, const float* __restrict__ c2b, int bb)
{
    __shared__ float cs[DD], xr[DD], x2[DD], hdn[DD], part[128];
    __shared__ float mv[2];
    int bl = blockIdx.x, t = threadIdx.x;
    int i = t & 63, half = t >> 6;
    if (t < DD) cs[t] = g_ctx[bl*DD + t];
    __syncthreads();

    // mha = ctx @ Wout^T + b ; x = Q + mha
    {
        const float4* wr = (const float4*)(opw + ((long)bb*DD + i)*DD) + half*8;
        const float4* uu = (const float4*)cs + half*8;
        float a = 0.f;
        #pragma unroll
        for (int kk = 0; kk < 8; kk++) {
            float4 w = wr[kk], x = uu[kk];
            a += w.x*x.x + w.y*x.y + w.z*x.z + w.w*x.w;
        }
        part[t] = a;
    }
    __syncthreads();
    if (t < DD)
        xr[t] = part[t] + part[t+64] + opb[bb*DD + t] + g_Q[bl*DD + t];
    __syncthreads();

    // LN(x) with fwd scale/bias
    if (t < 32) {
        float s = xr[t] + xr[t+32];
        #pragma unroll
        for (int o = 16; o; o >>= 1) s += __shfl_xor_sync(0xffffffffu, s, o);
        float mean = s * (1.f/64.f);
        float d0 = xr[t]-mean, d1 = xr[t+32]-mean;
        float vs = d0*d0 + d1*d1;
        #pragma unroll
        for (int o = 16; o; o >>= 1) vs += __shfl_xor_sync(0xffffffffu, vs, o);
        if (t == 0) { mv[0] = mean; mv[1] = rsqrtf(vs*(1.f/64.f) + 1e-8f); }
    }
    __syncthreads();
    if (t < DD)
        x2[t] = (xr[t] - mv[0]) * mv[1] * fs[bb*DD + t] + fb[bb*DD + t];
    __syncthreads();

    // hdn = relu(x2 @ conv1^T + b1)
    {
        const float4* wr = (const float4*)(c1w + ((long)bb*DD + i)*DD) + half*8;
        const float4* uu = (const float4*)x2 + half*8;
        float a = 0.f;
        #pragma unroll
        for (int kk = 0; kk < 8; kk++) {
            float4 w = wr[kk], x = uu[kk];
            a += w.x*x.x + w.y*x.y + w.z*x.z + w.w*x.w;
        }
        part[t] = a;
    }
    __syncthreads();
    if (t < DD) {
        float v = part[t] + part[t+64] + c1b[bb*DD + t];
        hdn[t] = v > 0.f ? v : 0.f;
    }
    __syncthreads();

    // x = x2 + hdn @ conv2^T + b2
    {
        const float4* wr = (const float4*)(c2w + ((long)bb*DD + i)*DD) + half*8;
        const float4* uu = (const float4*)hdn + half*8;
        float a = 0.f;
        #pragma unroll
        for (int kk = 0; kk < 8; kk++) {
            float4 w = wr[kk], x = uu[kk];
            a += w.x*x.x + w.y*x.y + w.z*x.z + w.w*x.w;
        }
        part[t] = a;
    }
    __syncthreads();
    if (t < DD)
        g_x[bl*DD + t] = x2[t] + part[t] + part[t+64] + c2b[bb*DD + t];
}

// ---------------- K7: last LN + logits ---------------------------------------
__global__ __launch_bounds__(64) void k_final(
    const float* __restrict__ E, const float* __restrict__ ls, const float* __restrict__ lb,
    const int* __restrict__ pos, const int* __restrict__ neg, float* __restrict__ out)
{
    __shared__ float xs[DD], red[DD];
    __shared__ float mv[2];
    int bl = blockIdx.x, t = threadIdx.x;
    xs[t] = g_x[bl*DD + t];
    __syncthreads();
    if (t < 32) {
        float s = xs[t] + xs[t+32];
        #pragma unroll
        for (int o = 16; o; o >>= 1) s += __shfl_xor_sync(0xffffffffu, s, o);
        float mean = s * (1.f/64.f);
        float d0 = xs[t]-mean, d1 = xs[t+32]-mean;
        float vs = d0*d0 + d1*d1;
        #pragma unroll
        for (int o = 16; o; o >>= 1) vs += __shfl_xor_sync(0xffffffffu, vs, o);
        if (t == 0) { mv[0] = mean; mv[1] = rsqrtf(vs*(1.f/64.f) + 1e-8f); }
    }
    __syncthreads();
    float lf = (xs[t] - mv[0]) * mv[1] * ls[t] + lb[t];
    float pe = lf * E[(long)pos[bl]*DD + t];
    float ne = lf * E[(long)neg[bl]*DD + t];
    red[t] = pe;
    __syncthreads();
    if (t < 32) {
        float s = red[t] + red[t+32];
        #pragma unroll
        for (int o = 16; o; o >>= 1) s += __shfl_xor_sync(0xffffffffu, s, o);
        if (t == 0) out[bl] = s;
    }
    __syncthreads();
    red[t] = ne;
    __syncthreads();
    if (t < 32) {
        float s = red[t] + red[t+32];
        #pragma unroll
        for (int o = 16; o; o >>= 1) s += __shfl_xor_sync(0xffffffffu, s, o);
        if (t == 0) out[BL + bl] = s;
    }
}

// ---------------- launch ------------------------------------------------------
extern "C" void kernel_launch(void* const* d_in, const int* in_sizes, int n_in,
                              void* d_out, int out_size)
{
    const float* uemb = (const float*)d_in[0];
    const float* E    = (const float*)d_in[1];
    const float* rel  = (const float*)d_in[2];
    const float* Wt   = (const float*)d_in[3];
    const float* W1   = (const float*)d_in[4];
    const float* W2   = (const float*)d_in[5];
    const float* pemb = (const float*)d_in[6];
    const float* lnas = (const float*)d_in[7];
    const float* lnab = (const float*)d_in[8];
    const float* ipw  = (const float*)d_in[9];
    const float* ipb  = (const float*)d_in[10];
    const float* opw  = (const float*)d_in[11];
    const float* opb  = (const float*)d_in[12];
    const float* fs   = (const float*)d_in[13];
    const float* fb   = (const float*)d_in[14];
    const float* c1w  = (const float*)d_in[15];
    const float* c1b  = (const float*)d_in[16];
    const float* c2w  = (const float*)d_in[17];
    const float* c2b  = (const float*)d_in[18];
    const float* lls  = (const float*)d_in[19];
    const float* llb  = (const float*)d_in[20];
    const int*   user = (const int*)d_in[21];
    const int*   seq  = (const int*)d_in[22];
    const int*   pos  = (const int*)d_in[23];
    const int*   neg  = (const int*)d_in[24];
    const int*   mh   = (const int*)d_in[25];
    const int*   mr   = (const int*)d_in[26];
    const int*   mt   = (const int*)d_in[27];
    float* out = (float*)d_out;

    k_init<<<BL, 64>>>(E, seq);
    for (int hop = 0; hop < NHOP; hop++) {
        k_vcomp<<<dim3(RR, 8), 256>>>(rel);
        k_hop<<<BL, 128>>>(E, Wt, mh, mr, mt, hop, hop == NHOP - 1);
    }
    k_scan<<<BB, 128>>>(W1, W2, uemb, user, pemb);
    for (int bb = 0; bb < NBLK; bb++) {
        k_lnqkv<<<BL, 128>>>(lnas, lnab, ipw, ipb, bb);
        k_attn<<<BB*HH, 256>>>();
        k_mlp<<<BL, 128>>>(opw, opb, fs, fb, c1w, c1b, c2w, c2b, bb);
    }
    k_final<<<BL, 64>>>(E, lls, llb, pos, neg, out);
}